// round 1
// baseline (speedup 1.0000x reference)
#include <cuda_runtime.h>
#include <math.h>

#define HD 64
#define MAXN 100000
#define MAXE 1200000
#define MAXB 1000
#define BN_EPS 1e-5f

// Scratch buffers (allocation-free rule: __device__ globals)
__device__ float g_agg1[MAXN * HD];
__device__ float g_h[MAXN * HD];
__device__ float g_agg2[MAXN * HD];
__device__ float g_pool[MAXB * HD];

__device__ __forceinline__ void red_add_f4(float* p, float4 v) {
    asm volatile("red.global.add.v4.f32 [%0], {%1, %2, %3, %4};"
                 :: "l"(p), "f"(v.x), "f"(v.y), "f"(v.z), "f"(v.w)
                 : "memory");
}

// ---------------------------------------------------------------------------
// K0: agg1 = x (copy), pool = 0
// ---------------------------------------------------------------------------
__global__ void init_kernel(const float4* __restrict__ x, int n4, int b4) {
    int i = blockIdx.x * blockDim.x + threadIdx.x;
    if (i < n4) ((float4*)g_agg1)[i] = x[i];
    if (i < b4) ((float4*)g_pool)[i] = make_float4(0.f, 0.f, 0.f, 0.f);
}

// ---------------------------------------------------------------------------
// K1: agg1[dst] += x[src]  (thread = (edge, 16B-chunk); chunk = float4)
// ---------------------------------------------------------------------------
__global__ void scatter1_kernel(const float* __restrict__ x,
                                const int* __restrict__ ei, int E) {
    int i = blockIdx.x * blockDim.x + threadIdx.x;
    if (i >= E * 16) return;
    int e = i >> 4, c = i & 15;
    int s = ei[e];
    int d = ei[E + e];
    float4 v = ((const float4*)x)[s * 16 + c];
    red_add_f4(g_agg1 + (d * 16 + c) * 4, v);
}

// K3: agg2[dst] += h[src]
__global__ void scatter2_kernel(const int* __restrict__ ei, int E) {
    int i = blockIdx.x * blockDim.x + threadIdx.x;
    if (i >= E * 16) return;
    int e = i >> 4, c = i & 15;
    int s = ei[e];
    int d = ei[E + e];
    float4 v = ((const float4*)g_h)[s * 16 + c];
    red_add_f4(g_agg2 + (d * 16 + c) * 4, v);
}

// ---------------------------------------------------------------------------
// K2: per-node MLP1: h = relu( relu(BN(agg1@W1a + b1a)) @ W1b + b1b )
//     also writes agg2 = h (init for second aggregation).
// Block = 256 threads = 64 rows x 4 col-quadrants, 16 outputs/thread.
// Dynamic shared: Wa[4096] Wb[4096] tile[64*65] s1[64] t1[64]  (~49.9 KB)
// ---------------------------------------------------------------------------
extern __shared__ float smem_dyn[];
__global__ void mlp1_kernel(const float* __restrict__ W1a, const float* __restrict__ b1a,
                            const float* __restrict__ g1,  const float* __restrict__ be1,
                            const float* __restrict__ m1,  const float* __restrict__ v1,
                            const float* __restrict__ W1b, const float* __restrict__ b1b,
                            int N) {
    float* Wa   = smem_dyn;               // 4096
    float* Wb   = smem_dyn + 4096;        // 4096
    float* tile = smem_dyn + 8192;        // 64*65 (padded rows: bank-conflict-free)
    float* s1   = tile + 64 * 65;         // 64
    float* t1   = s1 + 64;                // 64

    int tid = threadIdx.x;
    for (int i = tid; i < 4096; i += 256) { Wa[i] = W1a[i]; Wb[i] = W1b[i]; }
    if (tid < 64) {
        float s = g1[tid] * rsqrtf(v1[tid] + BN_EPS);
        s1[tid] = s;
        t1[tid] = be1[tid] - m1[tid] * s;
    }

    int rowBase = blockIdx.x * 64;
    for (int i = tid; i < 4096; i += 256) {
        int lr = i >> 6, lc = i & 63;
        int rr = rowBase + lr;
        tile[lr * 65 + lc] = (rr < N) ? g_agg1[rr * HD + lc] : 0.f;
    }
    __syncthreads();

    int r = tid >> 2, q = tid & 3, colBase = q * 16;
    float acc[16];

    // GEMM 1: tile @ W1a
    #pragma unroll
    for (int j = 0; j < 16; j++) acc[j] = b1a[colBase + j];
    #pragma unroll
    for (int k = 0; k < 64; k++) {
        float a = tile[r * 65 + k];
        const float4* w4 = (const float4*)(Wa + k * 64 + colBase);
        #pragma unroll
        for (int j4 = 0; j4 < 4; j4++) {
            float4 w = w4[j4];
            acc[j4 * 4 + 0] += a * w.x;
            acc[j4 * 4 + 1] += a * w.y;
            acc[j4 * 4 + 2] += a * w.z;
            acc[j4 * 4 + 3] += a * w.w;
        }
    }
    __syncthreads();   // all reads of tile done

    // BN + ReLU -> write back into tile as h1
    #pragma unroll
    for (int j = 0; j < 16; j++) {
        float y = acc[j] * s1[colBase + j] + t1[colBase + j];
        tile[r * 65 + colBase + j] = fmaxf(y, 0.f);
    }
    __syncthreads();

    // GEMM 2: h1 @ W1b
    #pragma unroll
    for (int j = 0; j < 16; j++) acc[j] = b1b[colBase + j];
    #pragma unroll
    for (int k = 0; k < 64; k++) {
        float a = tile[r * 65 + k];
        const float4* w4 = (const float4*)(Wb + k * 64 + colBase);
        #pragma unroll
        for (int j4 = 0; j4 < 4; j4++) {
            float4 w = w4[j4];
            acc[j4 * 4 + 0] += a * w.x;
            acc[j4 * 4 + 1] += a * w.y;
            acc[j4 * 4 + 2] += a * w.z;
            acc[j4 * 4 + 3] += a * w.w;
        }
    }

    int row = rowBase + r;
    if (row < N) {
        #pragma unroll
        for (int j4 = 0; j4 < 4; j4++) {
            float4 y = make_float4(fmaxf(acc[j4 * 4 + 0], 0.f),
                                   fmaxf(acc[j4 * 4 + 1], 0.f),
                                   fmaxf(acc[j4 * 4 + 2], 0.f),
                                   fmaxf(acc[j4 * 4 + 3], 0.f));
            ((float4*)(g_h    + row * HD + colBase))[j4] = y;
            ((float4*)(g_agg2 + row * HD + colBase))[j4] = y;
        }
    }
}

// ---------------------------------------------------------------------------
// K4: h2 = relu(BN(agg2@W2 + b2)); pool[batch[row]] += h2[row]  (REDG.128)
// ---------------------------------------------------------------------------
__global__ void mlp2_pool_kernel(const float* __restrict__ W2, const float* __restrict__ b2,
                                 const float* __restrict__ g2, const float* __restrict__ be2,
                                 const float* __restrict__ m2, const float* __restrict__ v2,
                                 const int* __restrict__ batch, int N) {
    __shared__ float Wa[4096];
    __shared__ float tile[64 * 65];
    __shared__ float s1[64], t1[64];

    int tid = threadIdx.x;
    for (int i = tid; i < 4096; i += 256) Wa[i] = W2[i];
    if (tid < 64) {
        float s = g2[tid] * rsqrtf(v2[tid] + BN_EPS);
        s1[tid] = s;
        t1[tid] = be2[tid] - m2[tid] * s;
    }

    int rowBase = blockIdx.x * 64;
    for (int i = tid; i < 4096; i += 256) {
        int lr = i >> 6, lc = i & 63;
        int rr = rowBase + lr;
        tile[lr * 65 + lc] = (rr < N) ? g_agg2[rr * HD + lc] : 0.f;
    }
    __syncthreads();

    int r = tid >> 2, q = tid & 3, colBase = q * 16;
    float acc[16];
    #pragma unroll
    for (int j = 0; j < 16; j++) acc[j] = b2[colBase + j];
    #pragma unroll
    for (int k = 0; k < 64; k++) {
        float a = tile[r * 65 + k];
        const float4* w4 = (const float4*)(Wa + k * 64 + colBase);
        #pragma unroll
        for (int j4 = 0; j4 < 4; j4++) {
            float4 w = w4[j4];
            acc[j4 * 4 + 0] += a * w.x;
            acc[j4 * 4 + 1] += a * w.y;
            acc[j4 * 4 + 2] += a * w.z;
            acc[j4 * 4 + 3] += a * w.w;
        }
    }

    int row = rowBase + r;
    if (row < N) {
        int b = batch[row];
        float* pp = g_pool + b * HD + colBase;
        #pragma unroll
        for (int j4 = 0; j4 < 4; j4++) {
            float4 y = make_float4(
                fmaxf(acc[j4 * 4 + 0] * s1[colBase + j4 * 4 + 0] + t1[colBase + j4 * 4 + 0], 0.f),
                fmaxf(acc[j4 * 4 + 1] * s1[colBase + j4 * 4 + 1] + t1[colBase + j4 * 4 + 1], 0.f),
                fmaxf(acc[j4 * 4 + 2] * s1[colBase + j4 * 4 + 2] + t1[colBase + j4 * 4 + 2], 0.f),
                fmaxf(acc[j4 * 4 + 3] * s1[colBase + j4 * 4 + 3] + t1[colBase + j4 * 4 + 3], 0.f));
            red_add_f4(pp + j4 * 4, y);
        }
    }
}

// ---------------------------------------------------------------------------
// K5: per graph: xt = relu(topo@Wt+bt); out = [pool, xt] @ Wc + bc
// One block (64 threads) per graph.
// ---------------------------------------------------------------------------
__global__ void final_kernel(const float* __restrict__ topo,
                             const float* __restrict__ Wt, const float* __restrict__ bt,
                             const float* __restrict__ Wc, const float* __restrict__ bc,
                             float* __restrict__ out, int B, int C) {
    int b = blockIdx.x;
    int t = threadIdx.x;   // 64
    __shared__ float comb[128];

    float acc = bt[t];
    #pragma unroll
    for (int k = 0; k < 64; k++)
        acc += topo[b * 64 + k] * Wt[k * 64 + t];
    comb[64 + t] = fmaxf(acc, 0.f);
    comb[t] = g_pool[b * HD + t];
    __syncthreads();

    if (t < C) {
        float o = bc[t];
        #pragma unroll
        for (int k = 0; k < 128; k++)
            o += comb[k] * Wc[k * C + t];
        out[b * C + t] = o;
    }
}

// ---------------------------------------------------------------------------
extern "C" void kernel_launch(void* const* d_in, const int* in_sizes, int n_in,
                              void* d_out, int out_size) {
    const float* x     = (const float*)d_in[0];
    const int*   ei    = (const int*)  d_in[1];
    const int*   batch = (const int*)  d_in[2];
    const float* topo  = (const float*)d_in[3];
    const float* W1a = (const float*)d_in[4];
    const float* b1a = (const float*)d_in[5];
    const float* g1  = (const float*)d_in[6];
    const float* be1 = (const float*)d_in[7];
    const float* m1  = (const float*)d_in[8];
    const float* v1  = (const float*)d_in[9];
    const float* W1b = (const float*)d_in[10];
    const float* b1b = (const float*)d_in[11];
    const float* W2  = (const float*)d_in[12];
    const float* b2  = (const float*)d_in[13];
    const float* g2  = (const float*)d_in[14];
    const float* be2 = (const float*)d_in[15];
    const float* m2  = (const float*)d_in[16];
    const float* v2  = (const float*)d_in[17];
    const float* Wt  = (const float*)d_in[18];
    const float* bt  = (const float*)d_in[19];
    const float* Wc  = (const float*)d_in[20];
    const float* bc  = (const float*)d_in[21];
    float* out = (float*)d_out;

    int N = in_sizes[0] / HD;        // nodes
    int E = in_sizes[1] / 2;         // edges
    int B = in_sizes[3] / HD;        // graphs (topo is [B,64])
    int C = out_size / B;            // classes

    // mlp1 needs ~49.9 KB dynamic shared
    static const int MLP1_SMEM = (4096 + 4096 + 64 * 65 + 128) * (int)sizeof(float);
    cudaFuncSetAttribute(mlp1_kernel, cudaFuncAttributeMaxDynamicSharedMemorySize, MLP1_SMEM);

    int n4 = N * 16, b4 = B * 16;
    int initN = (n4 > b4 ? n4 : b4);
    init_kernel<<<(initN + 255) / 256, 256>>>((const float4*)x, n4, b4);

    long long tot = (long long)E * 16;
    int sBlocks = (int)((tot + 255) / 256);
    scatter1_kernel<<<sBlocks, 256>>>(x, ei, E);

    int mBlocks = (N + 63) / 64;
    mlp1_kernel<<<mBlocks, 256, MLP1_SMEM>>>(W1a, b1a, g1, be1, m1, v1, W1b, b1b, N);

    scatter2_kernel<<<sBlocks, 256>>>(ei, E);

    mlp2_pool_kernel<<<mBlocks, 256>>>(W2, b2, g2, be2, m2, v2, batch, N);

    final_kernel<<<B, 64>>>(topo, Wt, bt, Wc, bc, out, B, C);
}

// round 2
// speedup vs baseline: 1.6979x; 1.6979x over previous
#include <cuda_runtime.h>
#include <math.h>

#define HD 64
#define MAXN 100000
#define MAXE 1200000
#define MAXB 1000
#define BN_EPS 1e-5f

typedef unsigned long long u64;

// Scratch (__device__ globals: allocation-free rule)
__device__ float g_h[MAXN * HD];
__device__ float g_pool[MAXB * HD];
__device__ int   g_deg[MAXN];
__device__ int   g_excl[MAXN];
__device__ int   g_bsum[1024];
__device__ int   g_rowptr[MAXN];
__device__ int   g_cursor[MAXN];
__device__ int   g_csr[MAXE];

__device__ __forceinline__ void red_add_f4(float* p, float4 v) {
    asm volatile("red.global.add.v4.f32 [%0], {%1, %2, %3, %4};"
                 :: "l"(p), "f"(v.x), "f"(v.y), "f"(v.z), "f"(v.w)
                 : "memory");
}
__device__ __forceinline__ u64 pack2(float x, float y) {
    u64 r; asm("mov.b64 %0, {%1, %2};" : "=l"(r) : "f"(x), "f"(y)); return r;
}
__device__ __forceinline__ float2 unpack2(u64 v) {
    float2 f; asm("mov.b64 {%0, %1}, %2;" : "=f"(f.x), "=f"(f.y) : "l"(v)); return f;
}
__device__ __forceinline__ void ffma2(u64& d, u64 a, u64 b) {
    asm("fma.rn.f32x2 %0, %1, %2, %0;" : "+l"(d) : "l"(a), "l"(b));
}

// ---------------------------------------------------------------------------
// K0: deg = 0, pool = 0
// ---------------------------------------------------------------------------
__global__ void zero_kernel(int N, int poolTot) {
    int i = blockIdx.x * blockDim.x + threadIdx.x;
    if (i < N) g_deg[i] = 0;
    if (i < poolTot) g_pool[i] = 0.f;
}

// K1: histogram of dst
__global__ void hist_kernel(const int* __restrict__ ei, int E) {
    int e = blockIdx.x * blockDim.x + threadIdx.x;
    if (e < E) atomicAdd(&g_deg[ei[E + e]], 1);
}

// K2a: per-block exclusive scan of deg (1024/block)
__global__ void scan1_kernel(int N) {
    int tid = threadIdx.x;
    int i = blockIdx.x * 1024 + tid;
    int v = (i < N) ? g_deg[i] : 0;
    int x = v;
    #pragma unroll
    for (int o = 1; o < 32; o <<= 1) {
        int y = __shfl_up_sync(0xFFFFFFFFu, x, o);
        if ((tid & 31) >= o) x += y;
    }
    __shared__ int ws[32];
    if ((tid & 31) == 31) ws[tid >> 5] = x;
    __syncthreads();
    if (tid < 32) {
        int y = ws[tid];
        #pragma unroll
        for (int o = 1; o < 32; o <<= 1) {
            int z = __shfl_up_sync(0xFFFFFFFFu, y, o);
            if (tid >= o) y += z;
        }
        ws[tid] = y;
    }
    __syncthreads();
    int base = (tid >= 32) ? ws[(tid >> 5) - 1] : 0;
    int incl = x + base;
    if (i < N) g_excl[i] = incl - v;
    if (tid == 1023) g_bsum[blockIdx.x] = incl;
}

// K2b: scan of block sums (single block; nb <= 1024)
__global__ void scan2_kernel(int nb) {
    int tid = threadIdx.x;
    int v = (tid < nb) ? g_bsum[tid] : 0;
    int x = v;
    #pragma unroll
    for (int o = 1; o < 32; o <<= 1) {
        int y = __shfl_up_sync(0xFFFFFFFFu, x, o);
        if ((tid & 31) >= o) x += y;
    }
    __shared__ int ws[32];
    if ((tid & 31) == 31) ws[tid >> 5] = x;
    __syncthreads();
    if (tid < 32) {
        int y = ws[tid];
        #pragma unroll
        for (int o = 1; o < 32; o <<= 1) {
            int z = __shfl_up_sync(0xFFFFFFFFu, y, o);
            if (tid >= o) y += z;
        }
        ws[tid] = y;
    }
    __syncthreads();
    int base = (tid >= 32) ? ws[(tid >> 5) - 1] : 0;
    int incl = x + base;
    if (tid < nb) g_bsum[tid] = incl - v;  // exclusive
}

// K2c: rowptr = excl + bsum[blk]; cursor = rowptr
__global__ void scan3_kernel(int N) {
    int i = blockIdx.x * blockDim.x + threadIdx.x;
    if (i < N) {
        int r = g_excl[i] + g_bsum[i >> 10];
        g_rowptr[i] = r;
        g_cursor[i] = r;
    }
}

// K3: bucket edges by dst: csr[pos] = src
__global__ void permute_kernel(const int* __restrict__ ei, int E) {
    int e = blockIdx.x * blockDim.x + threadIdx.x;
    if (e < E) {
        int d = ei[E + e];
        int pos = atomicAdd(&g_cursor[d], 1);
        g_csr[pos] = ei[e];
    }
}

// ---------------------------------------------------------------------------
// Gather helper: tile[lr] = src[g] + sum_{nb in CSR bucket g} src[nb]
// tile rows padded to 65 floats. Block covers 128 rows, 256 threads.
// ---------------------------------------------------------------------------
__device__ __forceinline__ void gather_tile(const float* __restrict__ src,
                                            float* tile, int rowBase, int N, int tid) {
    for (int task = tid; task < 128 * 16; task += 256) {
        int lr = task >> 4, c = task & 15;
        int g = rowBase + lr;
        float4 a = make_float4(0.f, 0.f, 0.f, 0.f);
        if (g < N) {
            a = ((const float4*)src)[g * 16 + c];
            int s = g_rowptr[g];
            int e = s + g_deg[g];
            int j = s;
            for (; j + 3 < e; j += 4) {
                int n0 = g_csr[j], n1 = g_csr[j + 1], n2 = g_csr[j + 2], n3 = g_csr[j + 3];
                float4 v0 = ((const float4*)src)[n0 * 16 + c];
                float4 v1 = ((const float4*)src)[n1 * 16 + c];
                float4 v2 = ((const float4*)src)[n2 * 16 + c];
                float4 v3 = ((const float4*)src)[n3 * 16 + c];
                a.x += (v0.x + v1.x) + (v2.x + v3.x);
                a.y += (v0.y + v1.y) + (v2.y + v3.y);
                a.z += (v0.z + v1.z) + (v2.z + v3.z);
                a.w += (v0.w + v1.w) + (v2.w + v3.w);
            }
            for (; j < e; j++) {
                int n0 = g_csr[j];
                float4 v0 = ((const float4*)src)[n0 * 16 + c];
                a.x += v0.x; a.y += v0.y; a.z += v0.z; a.w += v0.w;
            }
        }
        float* tp = tile + lr * 65 + c * 4;
        tp[0] = a.x; tp[1] = a.y; tp[2] = a.z; tp[3] = a.w;
    }
}

extern __shared__ float sdyn[];

// ---------------------------------------------------------------------------
// K4: mlp1: gather(x) -> GEMM(W1a)+BN+ReLU -> GEMM(W1b)+ReLU -> g_h
// Block = 256 thr = 128 rows (2 per thread) x 4 col-quadrants of 16.
// ---------------------------------------------------------------------------
__global__ __launch_bounds__(256) void mlp1_kernel(
    const float* __restrict__ x,
    const float* __restrict__ W1a, const float* __restrict__ b1a,
    const float* __restrict__ g1,  const float* __restrict__ be1,
    const float* __restrict__ m1,  const float* __restrict__ v1,
    const float* __restrict__ W1b, const float* __restrict__ b1b,
    int N) {
    float* Wa   = sdyn;                 // 4096
    float* Wb   = sdyn + 4096;          // 4096
    float* tile = sdyn + 8192;          // 128*65
    float* s1   = tile + 128 * 65;      // 64
    float* t1   = s1 + 64;              // 64

    int tid = threadIdx.x;
    for (int i = tid; i < 4096; i += 256) { Wa[i] = W1a[i]; Wb[i] = W1b[i]; }
    if (tid < 64) {
        float s = g1[tid] * rsqrtf(v1[tid] + BN_EPS);
        s1[tid] = s;
        t1[tid] = be1[tid] - m1[tid] * s;
    }
    int rowBase = blockIdx.x * 128;
    gather_tile(x, tile, rowBase, N, tid);
    __syncthreads();

    int rp = tid >> 2, q = tid & 3, colBase = q * 16;
    int r0 = rp, r1 = rp + 64;

    u64 acc0[8], acc1[8];
    #pragma unroll
    for (int j = 0; j < 8; j++) {
        u64 b = pack2(b1a[colBase + 2 * j], b1a[colBase + 2 * j + 1]);
        acc0[j] = b; acc1[j] = b;
    }
    #pragma unroll
    for (int k = 0; k < 64; k++) {
        float a0 = tile[r0 * 65 + k], a1 = tile[r1 * 65 + k];
        u64 A0 = pack2(a0, a0), A1 = pack2(a1, a1);
        const u64* w2 = (const u64*)(Wa + k * 64 + colBase);
        #pragma unroll
        for (int j = 0; j < 8; j++) {
            u64 w = w2[j];
            ffma2(acc0[j], A0, w);
            ffma2(acc1[j], A1, w);
        }
    }
    __syncthreads();
    // BN + ReLU -> tile (as h1)
    #pragma unroll
    for (int j = 0; j < 8; j++) {
        int c0 = colBase + 2 * j;
        float2 p = unpack2(acc0[j]);
        tile[r0 * 65 + c0]     = fmaxf(p.x * s1[c0]     + t1[c0],     0.f);
        tile[r0 * 65 + c0 + 1] = fmaxf(p.y * s1[c0 + 1] + t1[c0 + 1], 0.f);
        p = unpack2(acc1[j]);
        tile[r1 * 65 + c0]     = fmaxf(p.x * s1[c0]     + t1[c0],     0.f);
        tile[r1 * 65 + c0 + 1] = fmaxf(p.y * s1[c0 + 1] + t1[c0 + 1], 0.f);
    }
    __syncthreads();

    // GEMM2: h1 @ W1b
    #pragma unroll
    for (int j = 0; j < 8; j++) {
        u64 b = pack2(b1b[colBase + 2 * j], b1b[colBase + 2 * j + 1]);
        acc0[j] = b; acc1[j] = b;
    }
    #pragma unroll
    for (int k = 0; k < 64; k++) {
        float a0 = tile[r0 * 65 + k], a1 = tile[r1 * 65 + k];
        u64 A0 = pack2(a0, a0), A1 = pack2(a1, a1);
        const u64* w2 = (const u64*)(Wb + k * 64 + colBase);
        #pragma unroll
        for (int j = 0; j < 8; j++) {
            u64 w = w2[j];
            ffma2(acc0[j], A0, w);
            ffma2(acc1[j], A1, w);
        }
    }
    int gr0 = rowBase + r0, gr1 = rowBase + r1;
    if (gr0 < N) {
        #pragma unroll
        for (int j4 = 0; j4 < 4; j4++) {
            float2 pa = unpack2(acc0[j4 * 2]), pb = unpack2(acc0[j4 * 2 + 1]);
            float4 y = make_float4(fmaxf(pa.x, 0.f), fmaxf(pa.y, 0.f),
                                   fmaxf(pb.x, 0.f), fmaxf(pb.y, 0.f));
            ((float4*)(g_h + gr0 * HD + colBase))[j4] = y;
        }
    }
    if (gr1 < N) {
        #pragma unroll
        for (int j4 = 0; j4 < 4; j4++) {
            float2 pa = unpack2(acc1[j4 * 2]), pb = unpack2(acc1[j4 * 2 + 1]);
            float4 y = make_float4(fmaxf(pa.x, 0.f), fmaxf(pa.y, 0.f),
                                   fmaxf(pb.x, 0.f), fmaxf(pb.y, 0.f));
            ((float4*)(g_h + gr1 * HD + colBase))[j4] = y;
        }
    }
}

// ---------------------------------------------------------------------------
// K5: mlp2: gather(h) -> GEMM(W2)+BN+ReLU -> pool[batch] += (REDG.128)
// ---------------------------------------------------------------------------
__global__ __launch_bounds__(256) void mlp2_kernel(
    const float* __restrict__ W2, const float* __restrict__ b2,
    const float* __restrict__ g2, const float* __restrict__ be2,
    const float* __restrict__ m2, const float* __restrict__ v2,
    const int* __restrict__ batch, int N) {
    float* Wa   = sdyn;                 // 4096
    float* tile = sdyn + 4096;          // 128*65
    float* s1   = tile + 128 * 65;      // 64
    float* t1   = s1 + 64;              // 64

    int tid = threadIdx.x;
    for (int i = tid; i < 4096; i += 256) Wa[i] = W2[i];
    if (tid < 64) {
        float s = g2[tid] * rsqrtf(v2[tid] + BN_EPS);
        s1[tid] = s;
        t1[tid] = be2[tid] - m2[tid] * s;
    }
    int rowBase = blockIdx.x * 128;
    gather_tile(g_h, tile, rowBase, N, tid);
    __syncthreads();

    int rp = tid >> 2, q = tid & 3, colBase = q * 16;
    int r0 = rp, r1 = rp + 64;

    u64 acc0[8], acc1[8];
    #pragma unroll
    for (int j = 0; j < 8; j++) {
        u64 b = pack2(b2[colBase + 2 * j], b2[colBase + 2 * j + 1]);
        acc0[j] = b; acc1[j] = b;
    }
    #pragma unroll
    for (int k = 0; k < 64; k++) {
        float a0 = tile[r0 * 65 + k], a1 = tile[r1 * 65 + k];
        u64 A0 = pack2(a0, a0), A1 = pack2(a1, a1);
        const u64* w2 = (const u64*)(Wa + k * 64 + colBase);
        #pragma unroll
        for (int j = 0; j < 8; j++) {
            u64 w = w2[j];
            ffma2(acc0[j], A0, w);
            ffma2(acc1[j], A1, w);
        }
    }
    int gr0 = rowBase + r0, gr1 = rowBase + r1;
    if (gr0 < N) {
        int b = batch[gr0];
        float* pp = g_pool + b * HD + colBase;
        #pragma unroll
        for (int j4 = 0; j4 < 4; j4++) {
            int c0 = colBase + j4 * 4;
            float2 pa = unpack2(acc0[j4 * 2]), pb = unpack2(acc0[j4 * 2 + 1]);
            float4 y = make_float4(
                fmaxf(pa.x * s1[c0]     + t1[c0],     0.f),
                fmaxf(pa.y * s1[c0 + 1] + t1[c0 + 1], 0.f),
                fmaxf(pb.x * s1[c0 + 2] + t1[c0 + 2], 0.f),
                fmaxf(pb.y * s1[c0 + 3] + t1[c0 + 3], 0.f));
            red_add_f4(pp + j4 * 4, y);
        }
    }
    if (gr1 < N) {
        int b = batch[gr1];
        float* pp = g_pool + b * HD + colBase;
        #pragma unroll
        for (int j4 = 0; j4 < 4; j4++) {
            int c0 = colBase + j4 * 4;
            float2 pa = unpack2(acc1[j4 * 2]), pb = unpack2(acc1[j4 * 2 + 1]);
            float4 y = make_float4(
                fmaxf(pa.x * s1[c0]     + t1[c0],     0.f),
                fmaxf(pa.y * s1[c0 + 1] + t1[c0 + 1], 0.f),
                fmaxf(pb.x * s1[c0 + 2] + t1[c0 + 2], 0.f),
                fmaxf(pb.y * s1[c0 + 3] + t1[c0 + 3], 0.f));
            red_add_f4(pp + j4 * 4, y);
        }
    }
}

// ---------------------------------------------------------------------------
// K6: per graph: xt = relu(topo@Wt+bt); out = [pool, xt] @ Wc + bc
// ---------------------------------------------------------------------------
__global__ void final_kernel(const float* __restrict__ topo,
                             const float* __restrict__ Wt, const float* __restrict__ bt,
                             const float* __restrict__ Wc, const float* __restrict__ bc,
                             float* __restrict__ out, int B, int C) {
    int b = blockIdx.x;
    int t = threadIdx.x;   // 64
    __shared__ float comb[128];

    float acc = bt[t];
    #pragma unroll
    for (int k = 0; k < 64; k++)
        acc += topo[b * 64 + k] * Wt[k * 64 + t];
    comb[64 + t] = fmaxf(acc, 0.f);
    comb[t] = g_pool[b * HD + t];
    __syncthreads();

    if (t < C) {
        float o = bc[t];
        #pragma unroll
        for (int k = 0; k < 128; k++)
            o += comb[k] * Wc[k * C + t];
        out[b * C + t] = o;
    }
}

// ---------------------------------------------------------------------------
extern "C" void kernel_launch(void* const* d_in, const int* in_sizes, int n_in,
                              void* d_out, int out_size) {
    const float* x     = (const float*)d_in[0];
    const int*   ei    = (const int*)  d_in[1];
    const int*   batch = (const int*)  d_in[2];
    const float* topo  = (const float*)d_in[3];
    const float* W1a = (const float*)d_in[4];
    const float* b1a = (const float*)d_in[5];
    const float* g1  = (const float*)d_in[6];
    const float* be1 = (const float*)d_in[7];
    const float* m1  = (const float*)d_in[8];
    const float* v1  = (const float*)d_in[9];
    const float* W1b = (const float*)d_in[10];
    const float* b1b = (const float*)d_in[11];
    const float* W2  = (const float*)d_in[12];
    const float* b2  = (const float*)d_in[13];
    const float* g2  = (const float*)d_in[14];
    const float* be2 = (const float*)d_in[15];
    const float* m2  = (const float*)d_in[16];
    const float* v2  = (const float*)d_in[17];
    const float* Wt  = (const float*)d_in[18];
    const float* bt  = (const float*)d_in[19];
    const float* Wc  = (const float*)d_in[20];
    const float* bc  = (const float*)d_in[21];
    float* out = (float*)d_out;

    int N = in_sizes[0] / HD;        // nodes
    int E = in_sizes[1] / 2;         // edges
    int B = in_sizes[3] / HD;        // graphs
    int C = out_size / B;            // classes

    static const int MLP1_SMEM = (4096 + 4096 + 128 * 65 + 128) * (int)sizeof(float);
    static const int MLP2_SMEM = (4096 + 128 * 65 + 128) * (int)sizeof(float);
    cudaFuncSetAttribute(mlp1_kernel, cudaFuncAttributeMaxDynamicSharedMemorySize, MLP1_SMEM);
    cudaFuncSetAttribute(mlp2_kernel, cudaFuncAttributeMaxDynamicSharedMemorySize, MLP2_SMEM);

    int zTot = (N > B * HD) ? N : B * HD;
    zero_kernel<<<(zTot + 255) / 256, 256>>>(N, B * HD);

    hist_kernel<<<(E + 255) / 256, 256>>>(ei, E);

    int nb = (N + 1023) / 1024;
    scan1_kernel<<<nb, 1024>>>(N);
    scan2_kernel<<<1, 1024>>>(nb);
    scan3_kernel<<<(N + 255) / 256, 256>>>(N);

    permute_kernel<<<(E + 255) / 256, 256>>>(ei, E);

    int mBlocks = (N + 127) / 128;
    mlp1_kernel<<<mBlocks, 256, MLP1_SMEM>>>(x, W1a, b1a, g1, be1, m1, v1, W1b, b1b, N);
    mlp2_kernel<<<mBlocks, 256, MLP2_SMEM>>>(W2, b2, g2, be2, m2, v2, batch, N);

    final_kernel<<<B, 64>>>(topo, Wt, bt, Wc, bc, out, B, C);
}

// round 3
// speedup vs baseline: 1.7269x; 1.0171x over previous
#include <cuda_runtime.h>
#include <math.h>

#define HD 64
#define MAXN 100000
#define MAXE 1200000
#define MAXB 1000
#define BN_EPS 1e-5f
#define STAGE_CAP 2048

typedef unsigned long long u64;

// Scratch (__device__ globals: allocation-free rule)
__device__ float g_h[MAXN * HD];
__device__ float g_pool[MAXB * HD];
__device__ int   g_deg[MAXN];
__device__ int2  g_row2[MAXN];     // {rowptr, deg}
__device__ int   g_cursor[MAXN];
__device__ int   g_csr[MAXE];
__device__ u64   g_state[128];     // decoupled-lookback scan states

#define FLAG_AGG (1ull << 62)
#define FLAG_PRE (2ull << 62)

__device__ __forceinline__ void red_add_f4(float* p, float4 v) {
    asm volatile("red.global.add.v4.f32 [%0], {%1, %2, %3, %4};"
                 :: "l"(p), "f"(v.x), "f"(v.y), "f"(v.z), "f"(v.w)
                 : "memory");
}
__device__ __forceinline__ u64 pack2(float x, float y) {
    u64 r; asm("mov.b64 %0, {%1, %2};" : "=l"(r) : "f"(x), "f"(y)); return r;
}
__device__ __forceinline__ float2 unpack2(u64 v) {
    float2 f; asm("mov.b64 {%0, %1}, %2;" : "=f"(f.x), "=f"(f.y) : "l"(v)); return f;
}
__device__ __forceinline__ void ffma2(u64& d, u64 a, u64 b) {
    asm("fma.rn.f32x2 %0, %1, %2, %0;" : "+l"(d) : "l"(a), "l"(b));
}

// ---------------------------------------------------------------------------
// K0: deg = 0, pool = 0, scan states = 0
// ---------------------------------------------------------------------------
__global__ void zero_kernel(int N, int poolTot) {
    int i = blockIdx.x * blockDim.x + threadIdx.x;
    if (i < N) g_deg[i] = 0;
    if (i < poolTot) g_pool[i] = 0.f;
    if (i < 128) g_state[i] = 0ull;
}

// K1: histogram of dst
__global__ void hist_kernel(const int* __restrict__ ei, int E) {
    int e = blockIdx.x * blockDim.x + threadIdx.x;
    if (e < E) atomicAdd(&g_deg[ei[E + e]], 1);
}

// ---------------------------------------------------------------------------
// K2: single-pass exclusive scan (decoupled lookback), emits row2 + cursor
// ---------------------------------------------------------------------------
__global__ __launch_bounds__(1024) void scan_kernel(int N) {
    int b = blockIdx.x;
    int tid = threadIdx.x;
    int i = b * 1024 + tid;
    int v = (i < N) ? g_deg[i] : 0;
    int x = v;
    #pragma unroll
    for (int o = 1; o < 32; o <<= 1) {
        int y = __shfl_up_sync(0xFFFFFFFFu, x, o);
        if ((tid & 31) >= o) x += y;
    }
    __shared__ int ws[32];
    __shared__ int s_agg;
    __shared__ int s_excl;
    if ((tid & 31) == 31) ws[tid >> 5] = x;
    __syncthreads();
    if (tid < 32) {
        int y = ws[tid];
        #pragma unroll
        for (int o = 1; o < 32; o <<= 1) {
            int z = __shfl_up_sync(0xFFFFFFFFu, y, o);
            if (tid >= o) y += z;
        }
        ws[tid] = y;
    }
    __syncthreads();
    int base = (tid >= 32) ? ws[(tid >> 5) - 1] : 0;
    int incl = x + base;
    if (tid == 1023) s_agg = incl;
    __syncthreads();
    int agg = s_agg;

    // warp 0: publish + lookback
    if (tid < 32) {
        if (tid == 0) {
            u64 st = (b == 0 ? FLAG_PRE : FLAG_AGG) | (unsigned)agg;
            atomicExch(&g_state[b], st);
        }
        int excl = 0;
        if (b > 0) {
            int j = b - 1;
            bool done = false;
            while (!done) {
                int idx = j - tid;
                u64 s;
                if (idx >= 0) s = *(volatile u64*)&g_state[idx];
                else          s = FLAG_PRE;  // virtual prefix 0
                unsigned flag = (unsigned)(s >> 62);
                int val = (int)(unsigned)(s & 0xFFFFFFFFull);
                unsigned pmask = __ballot_sync(0xFFFFFFFFu, flag == 2u);
                unsigned rmask = __ballot_sync(0xFFFFFFFFu, flag >= 1u);
                if (pmask) {
                    int lead = __ffs(pmask) - 1;
                    unsigned need = (lead == 31) ? 0xFFFFFFFFu : ((1u << (lead + 1)) - 1u);
                    if ((rmask & need) == need) {
                        int contrib = (tid <= lead) ? val : 0;
                        #pragma unroll
                        for (int o = 16; o; o >>= 1)
                            contrib += __shfl_down_sync(0xFFFFFFFFu, contrib, o);
                        excl += __shfl_sync(0xFFFFFFFFu, contrib, 0);
                        done = true;
                    }
                } else if (rmask == 0xFFFFFFFFu) {
                    int contrib = val;
                    #pragma unroll
                    for (int o = 16; o; o >>= 1)
                        contrib += __shfl_down_sync(0xFFFFFFFFu, contrib, o);
                    excl += __shfl_sync(0xFFFFFFFFu, contrib, 0);
                    j -= 32;
                }
            }
            if (tid == 0)
                atomicExch(&g_state[b], FLAG_PRE | (unsigned)(excl + agg));
        }
        if (tid == 0) s_excl = excl;
    }
    __syncthreads();
    int rowp = s_excl + incl - v;
    if (i < N) {
        g_row2[i] = make_int2(rowp, v);
        g_cursor[i] = rowp;
    }
}

// K3: bucket edges by dst: csr[pos] = src
__global__ void permute_kernel(const int* __restrict__ ei, int E) {
    int e = blockIdx.x * blockDim.x + threadIdx.x;
    if (e < E) {
        int d = ei[E + e];
        int pos = atomicAdd(&g_cursor[d], 1);
        g_csr[pos] = ei[e];
    }
}

// ---------------------------------------------------------------------------
// Gather with smem-staged CSR segment.
// Block covers 128 rows; its CSR slice is contiguous -> coalesced stage.
// ---------------------------------------------------------------------------
__device__ __forceinline__ void gather_tile_staged(const float* __restrict__ src,
                                                   float* tile, int* sidx,
                                                   int rowBase, int N, int tid) {
    int rend = min(rowBase + 127, N - 1);
    int2 first = g_row2[rowBase];
    int2 last  = g_row2[rend];
    int segStart = first.x;
    int segLen = last.x + last.y - segStart;
    int stage = min(segLen, STAGE_CAP);
    for (int i = tid; i < stage; i += 256) sidx[i] = g_csr[segStart + i];
    __syncthreads();

    for (int task = tid; task < 128 * 16; task += 256) {
        int lr = task >> 4, c = task & 15;
        int g = rowBase + lr;
        float4 a = make_float4(0.f, 0.f, 0.f, 0.f);
        if (g < N) {
            a = ((const float4*)src)[g * 16 + c];
            int2 rd = g_row2[g];
            int s = rd.x - segStart;
            int e = s + rd.y;
            int eS = min(e, stage);
            int j = s;
            for (; j + 3 < eS; j += 4) {
                int n0 = sidx[j], n1 = sidx[j + 1], n2 = sidx[j + 2], n3 = sidx[j + 3];
                float4 v0 = ((const float4*)src)[n0 * 16 + c];
                float4 v1 = ((const float4*)src)[n1 * 16 + c];
                float4 v2 = ((const float4*)src)[n2 * 16 + c];
                float4 v3 = ((const float4*)src)[n3 * 16 + c];
                a.x += (v0.x + v1.x) + (v2.x + v3.x);
                a.y += (v0.y + v1.y) + (v2.y + v3.y);
                a.z += (v0.z + v1.z) + (v2.z + v3.z);
                a.w += (v0.w + v1.w) + (v2.w + v3.w);
            }
            for (; j < eS; j++) {
                float4 v0 = ((const float4*)src)[sidx[j] * 16 + c];
                a.x += v0.x; a.y += v0.y; a.z += v0.z; a.w += v0.w;
            }
            for (; j < e; j++) {   // overflow fallback (stage cap exceeded; ~never)
                float4 v0 = ((const float4*)src)[g_csr[segStart + j] * 16 + c];
                a.x += v0.x; a.y += v0.y; a.z += v0.z; a.w += v0.w;
            }
        }
        float* tp = tile + lr * 65 + c * 4;
        tp[0] = a.x; tp[1] = a.y; tp[2] = a.z; tp[3] = a.w;
    }
}

extern __shared__ float sdyn[];

// ---------------------------------------------------------------------------
// K4: mlp1: gather(x) -> GEMM(W1a)+BN+ReLU -> GEMM(W1b)+ReLU -> g_h
// idx stage overlays the W1b smem region; W1b is loaded after the gather
// (its global loads hide under GEMM1).
// ---------------------------------------------------------------------------
__global__ __launch_bounds__(256) void mlp1_kernel(
    const float* __restrict__ x,
    const float* __restrict__ W1a, const float* __restrict__ b1a,
    const float* __restrict__ g1,  const float* __restrict__ be1,
    const float* __restrict__ m1,  const float* __restrict__ v1,
    const float* __restrict__ W1b, const float* __restrict__ b1b,
    int N) {
    float* Wa   = sdyn;                 // 4096
    float* Wb   = sdyn + 4096;          // 4096 (first used as idx stage)
    float* tile = sdyn + 8192;          // 128*65
    float* s1   = tile + 128 * 65;      // 64
    float* t1   = s1 + 64;              // 64
    int* sidx   = (int*)Wb;

    int tid = threadIdx.x;
    for (int i = tid; i < 4096; i += 256) Wa[i] = W1a[i];
    if (tid < 64) {
        float s = g1[tid] * rsqrtf(v1[tid] + BN_EPS);
        s1[tid] = s;
        t1[tid] = be1[tid] - m1[tid] * s;
    }
    int rowBase = blockIdx.x * 128;
    gather_tile_staged(x, tile, sidx, rowBase, N, tid);
    __syncthreads();

    // load W1b into smem now (overlaps GEMM1 issue on other warps)
    #pragma unroll
    for (int i = 0; i < 4; i++) {
        ((float4*)Wb)[tid + 256 * i] = ((const float4*)W1b)[tid + 256 * i];
    }

    int rp = tid >> 2, q = tid & 3, colBase = q * 16;
    int r0 = rp, r1 = rp + 64;

    u64 acc0[8], acc1[8];
    #pragma unroll
    for (int j = 0; j < 8; j++) {
        u64 b = pack2(b1a[colBase + 2 * j], b1a[colBase + 2 * j + 1]);
        acc0[j] = b; acc1[j] = b;
    }
    #pragma unroll
    for (int k = 0; k < 64; k++) {
        float a0 = tile[r0 * 65 + k], a1 = tile[r1 * 65 + k];
        u64 A0 = pack2(a0, a0), A1 = pack2(a1, a1);
        const u64* w2 = (const u64*)(Wa + k * 64 + colBase);
        #pragma unroll
        for (int j = 0; j < 8; j++) {
            u64 w = w2[j];
            ffma2(acc0[j], A0, w);
            ffma2(acc1[j], A1, w);
        }
    }
    __syncthreads();   // tile reads + Wb stores complete
    // BN + ReLU -> tile (as h1)
    #pragma unroll
    for (int j = 0; j < 8; j++) {
        int c0 = colBase + 2 * j;
        float2 p = unpack2(acc0[j]);
        tile[r0 * 65 + c0]     = fmaxf(p.x * s1[c0]     + t1[c0],     0.f);
        tile[r0 * 65 + c0 + 1] = fmaxf(p.y * s1[c0 + 1] + t1[c0 + 1], 0.f);
        p = unpack2(acc1[j]);
        tile[r1 * 65 + c0]     = fmaxf(p.x * s1[c0]     + t1[c0],     0.f);
        tile[r1 * 65 + c0 + 1] = fmaxf(p.y * s1[c0 + 1] + t1[c0 + 1], 0.f);
    }
    __syncthreads();

    // GEMM2: h1 @ W1b
    #pragma unroll
    for (int j = 0; j < 8; j++) {
        u64 b = pack2(b1b[colBase + 2 * j], b1b[colBase + 2 * j + 1]);
        acc0[j] = b; acc1[j] = b;
    }
    #pragma unroll
    for (int k = 0; k < 64; k++) {
        float a0 = tile[r0 * 65 + k], a1 = tile[r1 * 65 + k];
        u64 A0 = pack2(a0, a0), A1 = pack2(a1, a1);
        const u64* w2 = (const u64*)(Wb + k * 64 + colBase);
        #pragma unroll
        for (int j = 0; j < 8; j++) {
            u64 w = w2[j];
            ffma2(acc0[j], A0, w);
            ffma2(acc1[j], A1, w);
        }
    }
    int gr0 = rowBase + r0, gr1 = rowBase + r1;
    if (gr0 < N) {
        #pragma unroll
        for (int j4 = 0; j4 < 4; j4++) {
            float2 pa = unpack2(acc0[j4 * 2]), pb = unpack2(acc0[j4 * 2 + 1]);
            float4 y = make_float4(fmaxf(pa.x, 0.f), fmaxf(pa.y, 0.f),
                                   fmaxf(pb.x, 0.f), fmaxf(pb.y, 0.f));
            ((float4*)(g_h + gr0 * HD + colBase))[j4] = y;
        }
    }
    if (gr1 < N) {
        #pragma unroll
        for (int j4 = 0; j4 < 4; j4++) {
            float2 pa = unpack2(acc1[j4 * 2]), pb = unpack2(acc1[j4 * 2 + 1]);
            float4 y = make_float4(fmaxf(pa.x, 0.f), fmaxf(pa.y, 0.f),
                                   fmaxf(pb.x, 0.f), fmaxf(pb.y, 0.f));
            ((float4*)(g_h + gr1 * HD + colBase))[j4] = y;
        }
    }
}

// ---------------------------------------------------------------------------
// K5: mlp2: gather(h) -> GEMM(W2)+BN+ReLU -> pool[batch] += (REDG.128)
// ---------------------------------------------------------------------------
__global__ __launch_bounds__(256) void mlp2_kernel(
    const float* __restrict__ W2, const float* __restrict__ b2,
    const float* __restrict__ g2, const float* __restrict__ be2,
    const float* __restrict__ m2, const float* __restrict__ v2,
    const int* __restrict__ batch, int N) {
    float* Wa   = sdyn;                 // 4096
    float* tile = sdyn + 4096;          // 128*65
    float* s1   = tile + 128 * 65;      // 64
    float* t1   = s1 + 64;              // 64
    int* sidx   = (int*)(t1 + 64);      // 2048

    int tid = threadIdx.x;
    for (int i = tid; i < 4096; i += 256) Wa[i] = W2[i];
    if (tid < 64) {
        float s = g2[tid] * rsqrtf(v2[tid] + BN_EPS);
        s1[tid] = s;
        t1[tid] = be2[tid] - m2[tid] * s;
    }
    int rowBase = blockIdx.x * 128;
    gather_tile_staged(g_h, tile, sidx, rowBase, N, tid);
    __syncthreads();

    int rp = tid >> 2, q = tid & 3, colBase = q * 16;
    int r0 = rp, r1 = rp + 64;

    u64 acc0[8], acc1[8];
    #pragma unroll
    for (int j = 0; j < 8; j++) {
        u64 b = pack2(b2[colBase + 2 * j], b2[colBase + 2 * j + 1]);
        acc0[j] = b; acc1[j] = b;
    }
    #pragma unroll
    for (int k = 0; k < 64; k++) {
        float a0 = tile[r0 * 65 + k], a1 = tile[r1 * 65 + k];
        u64 A0 = pack2(a0, a0), A1 = pack2(a1, a1);
        const u64* w2 = (const u64*)(Wa + k * 64 + colBase);
        #pragma unroll
        for (int j = 0; j < 8; j++) {
            u64 w = w2[j];
            ffma2(acc0[j], A0, w);
            ffma2(acc1[j], A1, w);
        }
    }
    int gr0 = rowBase + r0, gr1 = rowBase + r1;
    if (gr0 < N) {
        int b = batch[gr0];
        float* pp = g_pool + b * HD + colBase;
        #pragma unroll
        for (int j4 = 0; j4 < 4; j4++) {
            int c0 = colBase + j4 * 4;
            float2 pa = unpack2(acc0[j4 * 2]), pb = unpack2(acc0[j4 * 2 + 1]);
            float4 y = make_float4(
                fmaxf(pa.x * s1[c0]     + t1[c0],     0.f),
                fmaxf(pa.y * s1[c0 + 1] + t1[c0 + 1], 0.f),
                fmaxf(pb.x * s1[c0 + 2] + t1[c0 + 2], 0.f),
                fmaxf(pb.y * s1[c0 + 3] + t1[c0 + 3], 0.f));
            red_add_f4(pp + j4 * 4, y);
        }
    }
    if (gr1 < N) {
        int b = batch[gr1];
        float* pp = g_pool + b * HD + colBase;
        #pragma unroll
        for (int j4 = 0; j4 < 4; j4++) {
            int c0 = colBase + j4 * 4;
            float2 pa = unpack2(acc1[j4 * 2]), pb = unpack2(acc1[j4 * 2 + 1]);
            float4 y = make_float4(
                fmaxf(pa.x * s1[c0]     + t1[c0],     0.f),
                fmaxf(pa.y * s1[c0 + 1] + t1[c0 + 1], 0.f),
                fmaxf(pb.x * s1[c0 + 2] + t1[c0 + 2], 0.f),
                fmaxf(pb.y * s1[c0 + 3] + t1[c0 + 3], 0.f));
            red_add_f4(pp + j4 * 4, y);
        }
    }
}

// ---------------------------------------------------------------------------
// K6: per graph: xt = relu(topo@Wt+bt); out = [pool, xt] @ Wc + bc
// ---------------------------------------------------------------------------
__global__ void final_kernel(const float* __restrict__ topo,
                             const float* __restrict__ Wt, const float* __restrict__ bt,
                             const float* __restrict__ Wc, const float* __restrict__ bc,
                             float* __restrict__ out, int B, int C) {
    int b = blockIdx.x;
    int t = threadIdx.x;   // 64
    __shared__ float comb[128];

    float acc = bt[t];
    #pragma unroll
    for (int k = 0; k < 64; k++)
        acc += topo[b * 64 + k] * Wt[k * 64 + t];
    comb[64 + t] = fmaxf(acc, 0.f);
    comb[t] = g_pool[b * HD + t];
    __syncthreads();

    if (t < C) {
        float o = bc[t];
        #pragma unroll
        for (int k = 0; k < 128; k++)
            o += comb[k] * Wc[k * C + t];
        out[b * C + t] = o;
    }
}

// ---------------------------------------------------------------------------
extern "C" void kernel_launch(void* const* d_in, const int* in_sizes, int n_in,
                              void* d_out, int out_size) {
    const float* x     = (const float*)d_in[0];
    const int*   ei    = (const int*)  d_in[1];
    const int*   batch = (const int*)  d_in[2];
    const float* topo  = (const float*)d_in[3];
    const float* W1a = (const float*)d_in[4];
    const float* b1a = (const float*)d_in[5];
    const float* g1  = (const float*)d_in[6];
    const float* be1 = (const float*)d_in[7];
    const float* m1  = (const float*)d_in[8];
    const float* v1  = (const float*)d_in[9];
    const float* W1b = (const float*)d_in[10];
    const float* b1b = (const float*)d_in[11];
    const float* W2  = (const float*)d_in[12];
    const float* b2  = (const float*)d_in[13];
    const float* g2  = (const float*)d_in[14];
    const float* be2 = (const float*)d_in[15];
    const float* m2  = (const float*)d_in[16];
    const float* v2  = (const float*)d_in[17];
    const float* Wt  = (const float*)d_in[18];
    const float* bt  = (const float*)d_in[19];
    const float* Wc  = (const float*)d_in[20];
    const float* bc  = (const float*)d_in[21];
    float* out = (float*)d_out;

    int N = in_sizes[0] / HD;        // nodes
    int E = in_sizes[1] / 2;         // edges
    int B = in_sizes[3] / HD;        // graphs
    int C = out_size / B;            // classes

    static const int MLP1_SMEM = (4096 + 4096 + 128 * 65 + 128) * (int)sizeof(float);
    static const int MLP2_SMEM = (4096 + 128 * 65 + 128 + STAGE_CAP) * (int)sizeof(float);
    cudaFuncSetAttribute(mlp1_kernel, cudaFuncAttributeMaxDynamicSharedMemorySize, MLP1_SMEM);
    cudaFuncSetAttribute(mlp2_kernel, cudaFuncAttributeMaxDynamicSharedMemorySize, MLP2_SMEM);

    int zTot = (N > B * HD) ? N : B * HD;
    zero_kernel<<<(zTot + 255) / 256, 256>>>(N, B * HD);

    hist_kernel<<<(E + 255) / 256, 256>>>(ei, E);

    int nb = (N + 1023) / 1024;
    scan_kernel<<<nb, 1024>>>(N);

    permute_kernel<<<(E + 255) / 256, 256>>>(ei, E);

    int mBlocks = (N + 127) / 128;
    mlp1_kernel<<<mBlocks, 256, MLP1_SMEM>>>(x, W1a, b1a, g1, be1, m1, v1, W1b, b1b, N);
    mlp2_kernel<<<mBlocks, 256, MLP2_SMEM>>>(W2, b2, g2, be2, m2, v2, batch, N);

    final_kernel<<<B, 64>>>(topo, Wt, bt, Wc, bc, out, B, C);
}